// round 7
// baseline (speedup 1.0000x reference)
#include <cuda_runtime.h>
#include <cstdint>

#define NN 50000
#define EE 400000
#define INF_ 256
#define OUTF 64
#define EDF 64
#define HH 4
#define HOUT 256   // H*OUT

// ---------------- device scratch (static, no allocs) ----------------
__device__ float g_W2[INF_ * HOUT];      // W_fc transposed: [i][h*64+o]
__device__ float g_Wi2[HOUT];
__device__ float g_Wj2[HOUT];
__device__ float g_v[HH * EDF];          // W_eatt[h] @ We[h]
__device__ float g_catt[HH];             // b_att + b_eatt . We
__device__ float g_z[(size_t)NN * HOUT]; // z[n][h*64+o]
__device__ float g_ai[NN * HH];
__device__ float g_aj[NN * HH];
__device__ float g_ex[(size_t)EE * HH];  // exp(logit) [e][h], later normalized alpha
__device__ float g_s[(size_t)NN * HH * EDF]; // gathered alpha-weighted edge_attr
// CSR
__device__ int g_deg[NN];
__device__ int g_off[NN + 1];
__device__ int g_cur[NN];
__device__ int g_bsum[256];
__device__ int g_csr_src[EE];
__device__ int g_csr_eid[EE];

// ---------------- K0: init + tiny precomputes ----------------
__global__ void __launch_bounds__(256) k_init(
    const float* __restrict__ W_fc, const float* __restrict__ W_att,
    const float* __restrict__ b_att, const float* __restrict__ W_eatt,
    const float* __restrict__ b_eatt)
{
    int idx = blockIdx.x * 256 + threadIdx.x;   // 0 .. 65535
    if (idx < NN) g_deg[idx] = 0;
    if (idx < INF_ * HOUT) {
        int i = idx / HOUT, c = idx % HOUT;
        int h = c / OUTF, o = c % OUTF;
        g_W2[i * HOUT + c] = W_fc[((size_t)h * INF_ + i) * OUTF + o];
    }
    if (idx < HOUT) {
        int h = idx / OUTF, o = idx % OUTF;
        g_Wi2[idx] = W_att[h * 192 + o];
        g_Wj2[idx] = W_att[h * 192 + 64 + o];
    }
    if (idx < HH * EDF) {
        int h = idx / EDF, f = idx % EDF;
        float s = 0.0f;
        #pragma unroll 8
        for (int g = 0; g < EDF; g++)
            s += W_eatt[((size_t)h * EDF + f) * EDF + g] * W_att[h * 192 + 128 + g];
        g_v[idx] = s;
    }
    if (idx < HH) {
        int h = idx;
        float s = b_att[h];
        for (int g = 0; g < EDF; g++)
            s += b_eatt[h * EDF + g] * W_att[h * 192 + 128 + g];
        g_catt[h] = s;
    }
}

// ---------------- K1: node GEMM z = x @ W2 + b, fused ai/aj dots ----------------
__global__ void __launch_bounds__(256) k_node_gemm(
    const float* __restrict__ x, const float* __restrict__ b_fc)
{
    __shared__ __align__(16) float As[64 * 20];
    __shared__ __align__(16) float Bs[16 * 64];
    const int head = blockIdx.y;
    const int rowbase = blockIdx.x * 64;
    const int colbase = head * 64;
    const int tid = threadIdx.x;
    const int tx = tid & 15, ty = tid >> 4;

    float c[4][4];
    #pragma unroll
    for (int i = 0; i < 4; i++)
        #pragma unroll
        for (int j = 0; j < 4; j++) c[i][j] = 0.0f;

    const int lr = tid >> 2;
    const int lq = (tid & 3) * 4;
    const int bk = tid >> 4;
    const int bn = (tid & 15) * 4;

    for (int kb = 0; kb < INF_; kb += 16) {
        float4 av = make_float4(0.f, 0.f, 0.f, 0.f);
        int arow = rowbase + lr;
        if (arow < NN) av = *(const float4*)(x + (size_t)arow * INF_ + kb + lq);
        *(float4*)(As + lr * 20 + lq) = av;
        float4 bv = *(const float4*)(g_W2 + (size_t)(kb + bk) * HOUT + colbase + bn);
        *(float4*)(Bs + bk * 64 + bn) = bv;
        __syncthreads();
        #pragma unroll
        for (int kk = 0; kk < 16; kk++) {
            float a0 = As[(ty * 4 + 0) * 20 + kk];
            float a1 = As[(ty * 4 + 1) * 20 + kk];
            float a2 = As[(ty * 4 + 2) * 20 + kk];
            float a3 = As[(ty * 4 + 3) * 20 + kk];
            float4 b = *(const float4*)(Bs + kk * 64 + tx * 4);
            c[0][0] += a0 * b.x; c[0][1] += a0 * b.y; c[0][2] += a0 * b.z; c[0][3] += a0 * b.w;
            c[1][0] += a1 * b.x; c[1][1] += a1 * b.y; c[1][2] += a1 * b.z; c[1][3] += a1 * b.w;
            c[2][0] += a2 * b.x; c[2][1] += a2 * b.y; c[2][2] += a2 * b.z; c[2][3] += a2 * b.w;
            c[3][0] += a3 * b.x; c[3][1] += a3 * b.y; c[3][2] += a3 * b.z; c[3][3] += a3 * b.w;
        }
        __syncthreads();
    }

    float4 bb = *(const float4*)(b_fc + colbase + tx * 4);
    float4 wi = *(const float4*)(g_Wi2 + colbase + tx * 4);
    float4 wj = *(const float4*)(g_Wj2 + colbase + tx * 4);

    #pragma unroll
    for (int i = 0; i < 4; i++) {
        int row = rowbase + ty * 4 + i;
        float4 r;
        r.x = c[i][0] + bb.x; r.y = c[i][1] + bb.y;
        r.z = c[i][2] + bb.z; r.w = c[i][3] + bb.w;
        float si = r.x * wi.x + r.y * wi.y + r.z * wi.z + r.w * wi.w;
        float sj = r.x * wj.x + r.y * wj.y + r.z * wj.z + r.w * wj.w;
        #pragma unroll
        for (int off = 8; off >= 1; off >>= 1) {
            si += __shfl_xor_sync(0xffffffffu, si, off);
            sj += __shfl_xor_sync(0xffffffffu, sj, off);
        }
        if (row < NN) {
            *(float4*)(g_z + (size_t)row * HOUT + colbase + tx * 4) = r;
            if (tx == 0) {
                g_ai[row * HH + head] = si;
                g_aj[row * HH + head] = sj;
            }
        }
    }
}

// ---------------- K2: edge logits + leaky relu + exp; fused degree histogram ----------------
__global__ void __launch_bounds__(128) k_edge_logits(
    const float* __restrict__ edge_attr, const int* __restrict__ ei)
{
    __shared__ float sm_ea[128 * 65];
    __shared__ float sm_v[HH * EDF];
    __shared__ float sm_c[HH];
    const int t = threadIdx.x;
    const int ebase = blockIdx.x * 128;

    #pragma unroll
    for (int j = 0; j < 16; j++) {
        int f4 = t + 128 * j;
        int eeI = f4 >> 4, qf = (f4 & 15) * 4;
        float4 v = *(const float4*)(edge_attr + (size_t)(ebase + eeI) * EDF + qf);
        float* p = sm_ea + eeI * 65 + qf;
        p[0] = v.x; p[1] = v.y; p[2] = v.z; p[3] = v.w;
    }
    if (t < HH * EDF) sm_v[t] = g_v[t];
    if (t + 128 < HH * EDF) sm_v[t + 128] = g_v[t + 128];
    if (t < HH) sm_c[t] = g_catt[t];
    __syncthreads();

    int ge = ebase + t;
    int src = ei[ge];
    int dst = ei[EE + ge];
    float4 ai4 = *(const float4*)(g_ai + dst * HH);
    float4 aj4 = *(const float4*)(g_aj + src * HH);
    float ain[4] = {ai4.x, ai4.y, ai4.z, ai4.w};
    float ajn[4] = {aj4.x, aj4.y, aj4.z, aj4.w};

    float exv[4];
    #pragma unroll
    for (int h = 0; h < HH; h++) {
        float acc = sm_c[h];
        #pragma unroll 16
        for (int f = 0; f < EDF; f++)
            acc += sm_ea[t * 65 + f] * sm_v[h * EDF + f];
        float a = acc + ain[h] + ajn[h];
        float e = (a > 0.0f) ? a : 0.2f * a;
        exv[h] = __expf(e);
    }
    *(float4*)(g_ex + (size_t)ge * 4) =
        make_float4(exv[0], exv[1], exv[2], exv[3]);
    atomicAdd(&g_deg[dst], 1);
}

// ---------------- CSR build: 3-stage scan + fill ----------------
__global__ void __launch_bounds__(256) k_scan_a()
{
    __shared__ int sh[256];
    int t = threadIdx.x;
    int idx = blockIdx.x * 256 + t;
    int v = (idx < NN) ? g_deg[idx] : 0;
    sh[t] = v;
    __syncthreads();
    #pragma unroll
    for (int d = 1; d < 256; d <<= 1) {
        int x = (t >= d) ? sh[t - d] : 0;
        __syncthreads();
        if (t >= d) sh[t] += x;
        __syncthreads();
    }
    if (idx < NN) g_off[idx] = sh[t] - v;       // exclusive within chunk
    if (t == 255) g_bsum[blockIdx.x] = sh[255]; // chunk total
}

__global__ void __launch_bounds__(256) k_scan_b(int nblocks)
{
    __shared__ int sh[256];
    int t = threadIdx.x;
    int v = (t < nblocks) ? g_bsum[t] : 0;
    sh[t] = v;
    __syncthreads();
    #pragma unroll
    for (int d = 1; d < 256; d <<= 1) {
        int x = (t >= d) ? sh[t - d] : 0;
        __syncthreads();
        if (t >= d) sh[t] += x;
        __syncthreads();
    }
    if (t < nblocks) g_bsum[t] = sh[t] - v;     // exclusive over chunk totals
}

__global__ void __launch_bounds__(256) k_scan_c()
{
    int idx = blockIdx.x * 256 + threadIdx.x;
    if (idx < NN) {
        int o = g_off[idx] + g_bsum[blockIdx.x];
        g_off[idx] = o;
        g_cur[idx] = o;
    }
    if (idx == 0) g_off[NN] = EE;
}

__global__ void __launch_bounds__(256) k_fill(const int* __restrict__ ei)
{
    int e = blockIdx.x * 256 + threadIdx.x;
    if (e >= EE) return;
    int src = ei[e];
    int dst = ei[EE + e];
    int pos = atomicAdd(&g_cur[dst], 1);
    g_csr_src[pos] = src;
    g_csr_eid[pos] = e;
}

// ---------------- K3: gather — softmax denom + out + s, no atomics ----------------
__global__ void __launch_bounds__(256) k_gather(
    const float* __restrict__ edge_attr, float* __restrict__ out)
{
    const int t = threadIdx.x;
    const int lane64 = t & 63;
    const int nl = t >> 6;
    const int n = blockIdx.x * 4 + nl;
    const int h = lane64 >> 4;
    const int q = lane64 & 15;

    const int beg = g_off[n];
    const int end = g_off[n + 1];

    // pass 1: per-(node,head) softmax denominator
    float ss = 0.0f;
    for (int i = beg + q; i < end; i += 16)
        ss += g_ex[(size_t)g_csr_eid[i] * 4 + h];
    #pragma unroll
    for (int o = 8; o >= 1; o >>= 1)
        ss += __shfl_xor_sync(0xffffffffu, ss, o, 16);
    float inv = 1.0f / ss;   // only used when end > beg

    // pass 2: gather messages
    float4 accO = make_float4(0.f, 0.f, 0.f, 0.f);
    float4 accS = make_float4(0.f, 0.f, 0.f, 0.f);
    for (int i = beg; i < end; i++) {
        int eid = g_csr_eid[i];
        int src = g_csr_src[i];
        float al = g_ex[(size_t)eid * 4 + h] * inv;
        if (q == 0) g_ex[(size_t)eid * 4 + h] = al;  // store normalized alpha
        float4 z4 = *(const float4*)(g_z + (size_t)src * HOUT + lane64 * 4);
        accO.x = fmaf(al, z4.x, accO.x);
        accO.y = fmaf(al, z4.y, accO.y);
        accO.z = fmaf(al, z4.z, accO.z);
        accO.w = fmaf(al, z4.w, accO.w);
        float4 e4 = *(const float4*)(edge_attr + (size_t)eid * EDF + q * 4);
        accS.x = fmaf(al, e4.x, accS.x);
        accS.y = fmaf(al, e4.y, accS.y);
        accS.z = fmaf(al, e4.z, accS.z);
        accS.w = fmaf(al, e4.w, accS.w);
    }
    *(float4*)(out + (size_t)n * HOUT + lane64 * 4) = accO;
    *(float4*)(g_s + (((size_t)n * HH + h) * EDF) + q * 4) = accS;
}

// ---------------- K4: transpose normalized alpha [e][h] -> [h][E] ----------------
__global__ void __launch_bounds__(256) k_alpha_t(float* __restrict__ alphaOut)
{
    int e = blockIdx.x * 256 + threadIdx.x;
    if (e >= EE) return;
    float4 a4 = *(const float4*)(g_ex + (size_t)e * 4);
    alphaOut[0 * (size_t)EE + e] = a4.x;
    alphaOut[1 * (size_t)EE + e] = a4.y;
    alphaOut[2 * (size_t)EE + e] = a4.z;
    alphaOut[3 * (size_t)EE + e] = a4.w;
}

// ---------------- K5: out += s @ W_edge + (deg>0 ? b_edge : 0) ----------------
__global__ void __launch_bounds__(256) k_out_gemm(
    const float* __restrict__ W_edge, const float* __restrict__ b_edge,
    float* __restrict__ out)
{
    __shared__ __align__(16) float As[64 * 68];
    __shared__ __align__(16) float Bs[64 * 64];
    const int h = blockIdx.y;
    const int rowbase = blockIdx.x * 64;
    const int tid = threadIdx.x;
    const int tx = tid & 15, ty = tid >> 4;

    {
        const int lr = tid >> 2;
        const int lq = (tid & 3) * 4;
        #pragma unroll
        for (int j = 0; j < 4; j++) {
            int f = lq + j * 16;
            int row = rowbase + lr;
            float4 v = make_float4(0.f, 0.f, 0.f, 0.f);
            if (row < NN)
                v = *(const float4*)(g_s + (((size_t)row * HH + h) * EDF) + f);
            *(float4*)(As + lr * 68 + f) = v;
        }
        const int fr = tid >> 4;
        const int qn = (tid & 15) * 4;
        #pragma unroll
        for (int j = 0; j < 4; j++) {
            int fk = fr + j * 16;
            float4 w = *(const float4*)(W_edge + ((size_t)h * EDF + fk) * OUTF + qn);
            *(float4*)(Bs + fk * 64 + qn) = w;
        }
    }
    __syncthreads();

    float c[4][4];
    #pragma unroll
    for (int i = 0; i < 4; i++)
        #pragma unroll
        for (int j = 0; j < 4; j++) c[i][j] = 0.0f;

    #pragma unroll 16
    for (int kk = 0; kk < EDF; kk++) {
        float a0 = As[(ty * 4 + 0) * 68 + kk];
        float a1 = As[(ty * 4 + 1) * 68 + kk];
        float a2 = As[(ty * 4 + 2) * 68 + kk];
        float a3 = As[(ty * 4 + 3) * 68 + kk];
        float4 b = *(const float4*)(Bs + kk * 64 + tx * 4);
        c[0][0] += a0 * b.x; c[0][1] += a0 * b.y; c[0][2] += a0 * b.z; c[0][3] += a0 * b.w;
        c[1][0] += a1 * b.x; c[1][1] += a1 * b.y; c[1][2] += a1 * b.z; c[1][3] += a1 * b.w;
        c[2][0] += a2 * b.x; c[2][1] += a2 * b.y; c[2][2] += a2 * b.z; c[2][3] += a2 * b.w;
        c[3][0] += a3 * b.x; c[3][1] += a3 * b.y; c[3][2] += a3 * b.z; c[3][3] += a3 * b.w;
    }

    float4 be = *(const float4*)(b_edge + h * OUTF + tx * 4);

    #pragma unroll
    for (int i = 0; i < 4; i++) {
        int row = rowbase + ty * 4 + i;
        if (row < NN) {
            float flag = (g_off[row + 1] - g_off[row]) > 0 ? 1.0f : 0.0f;
            float* po = out + (size_t)row * HOUT + h * OUTF + tx * 4;
            float4 o4 = *(const float4*)po;
            o4.x += c[i][0] + flag * be.x;
            o4.y += c[i][1] + flag * be.y;
            o4.z += c[i][2] + flag * be.z;
            o4.w += c[i][3] + flag * be.w;
            *(float4*)po = o4;
        }
    }
}

// ---------------- launch ----------------
extern "C" void kernel_launch(void* const* d_in, const int* in_sizes, int n_in,
                              void* d_out, int out_size)
{
    const float* x      = (const float*)d_in[0];
    const int*   ei     = (const int*)d_in[1];
    const float* eattr  = (const float*)d_in[2];
    const float* W_fc   = (const float*)d_in[3];
    const float* b_fc   = (const float*)d_in[4];
    const float* W_att  = (const float*)d_in[5];
    const float* b_att  = (const float*)d_in[6];
    const float* W_edge = (const float*)d_in[7];
    const float* b_edge = (const float*)d_in[8];
    const float* W_eatt = (const float*)d_in[9];
    const float* b_eatt = (const float*)d_in[10];
    float* out = (float*)d_out;
    float* alphaOut = out + (size_t)NN * HOUT;

    const int SCAN_BLKS = (NN + 255) / 256;  // 196

    k_init<<<256, 256>>>(W_fc, W_att, b_att, W_eatt, b_eatt);
    k_node_gemm<<<dim3((NN + 63) / 64, HH), 256>>>(x, b_fc);
    k_edge_logits<<<EE / 128, 128>>>(eattr, ei);
    k_scan_a<<<SCAN_BLKS, 256>>>();
    k_scan_b<<<1, 256>>>(SCAN_BLKS);
    k_scan_c<<<SCAN_BLKS, 256>>>();
    k_fill<<<(EE + 255) / 256, 256>>>(ei);
    k_gather<<<NN / 4, 256>>>(eattr, out);
    k_alpha_t<<<(EE + 255) / 256, 256>>>(alphaOut);
    k_out_gemm<<<dim3((NN + 63) / 64, HH), 256>>>(W_edge, b_edge, out);
}

// round 9
// speedup vs baseline: 1.2444x; 1.2444x over previous
#include <cuda_runtime.h>
#include <cstdint>

#define NN 50000
#define EE 400000
#define INF_ 256
#define OUTF 64
#define EDF 64
#define HH 4
#define HOUT 256   // H*OUT

// ---------------- device scratch (static, no allocs) ----------------
__device__ float g_Wb[INF_ * HOUT];      // B matrix: [n=h*64+o][k]
__device__ float g_Wi2[HOUT];
__device__ float g_Wj2[HOUT];
__device__ float g_v[HH * EDF];          // W_eatt[h] @ We[h]
__device__ float g_catt[HH];             // b_att + b_eatt . We
__device__ float g_z[(size_t)NN * HOUT]; // z[n][h*64+o]
__device__ float g_ai[NN * HH];
__device__ float g_aj[NN * HH];
__device__ float g_ex[(size_t)EE * HH];  // exp(logit) [e][h], later normalized alpha
__device__ float g_s[(size_t)NN * HH * EDF];
// CSR
__device__ int g_deg[NN];
__device__ int g_off[NN + 1];
__device__ int g_cur[NN];
__device__ int g_bsum[256];
__device__ int g_csr_src[EE];
__device__ int g_csr_eid[EE];

__device__ __forceinline__ uint32_t tf32_of(float f) {
    uint32_t r;
    asm("cvt.rna.tf32.f32 %0, %1;" : "=r"(r) : "f"(f));
    return r;
}

__device__ __forceinline__ void mma_tf32(float* d, const uint32_t* a, const uint32_t* b) {
    asm volatile(
        "mma.sync.aligned.m16n8k8.row.col.f32.tf32.tf32.f32 "
        "{%0,%1,%2,%3}, {%4,%5,%6,%7}, {%8,%9}, {%0,%1,%2,%3};"
        : "+f"(d[0]), "+f"(d[1]), "+f"(d[2]), "+f"(d[3])
        : "r"(a[0]), "r"(a[1]), "r"(a[2]), "r"(a[3]), "r"(b[0]), "r"(b[1]));
}

// ---------------- K0: init + tiny precomputes ----------------
__global__ void __launch_bounds__(256) k_init(
    const float* __restrict__ W_fc, const float* __restrict__ W_att,
    const float* __restrict__ b_att, const float* __restrict__ W_eatt,
    const float* __restrict__ b_eatt)
{
    int idx = blockIdx.x * 256 + threadIdx.x;   // 0 .. 65535
    if (idx < NN) g_deg[idx] = 0;
    {
        int n = idx >> 8, k = idx & 255;
        int h = n >> 6, o = n & 63;
        g_Wb[n * 256 + k] = W_fc[((size_t)h * INF_ + k) * OUTF + o];
    }
    if (idx < HOUT) {
        int h = idx / OUTF, o = idx % OUTF;
        g_Wi2[idx] = W_att[h * 192 + o];
        g_Wj2[idx] = W_att[h * 192 + 64 + o];
    }
    if (idx < HH * EDF) {
        int h = idx / EDF, f = idx % EDF;
        float s = 0.0f;
        #pragma unroll 8
        for (int g = 0; g < EDF; g++)
            s += W_eatt[((size_t)h * EDF + f) * EDF + g] * W_att[h * 192 + 128 + g];
        g_v[idx] = s;
    }
    if (idx < HH) {
        int h = idx;
        float s = b_att[h];
        for (int g = 0; g < EDF; g++)
            s += b_eatt[h * EDF + g] * W_att[h * 192 + 128 + g];
        g_catt[h] = s;
    }
}

// ---------------- K1: tf32 mma.sync node GEMM: z = x @ Wb^T + b ----------------
// CTA 128M x 128N, 8 warps (2M x 4N), warp tile 64x32, K chunks of 32.
// smem K-major [k][m] stride 132 (conflict-free fragment LDS).
#define KC 32
#define SSTR 132
#define STG_F (KC * SSTR)          // floats per stage per operand

__global__ void __launch_bounds__(256) k_node_tc(
    const float* __restrict__ x, const float* __restrict__ b_fc)
{
    extern __shared__ uint32_t smem[];
    uint32_t* As = smem;                 // [2][KC][SSTR]
    uint32_t* Bs = smem + 2 * STG_F;     // [2][KC][SSTR]
    __shared__ float s_bias[128];

    const int tid = threadIdx.x;
    const int wid = tid >> 5;
    const int lane = tid & 31;
    const int wm = wid >> 2;             // 0..1
    const int wn = wid & 3;              // 0..3
    const int rowbase = blockIdx.x * 128;
    const int nbase = blockIdx.y * 128;

    const int lrow = tid >> 1;           // 0..127
    const int lko  = (tid & 1) * 16;     // 0 or 16

    if (tid < 128) s_bias[tid] = b_fc[nbase + tid];

    float acc[4][4][4];
    #pragma unroll
    for (int i = 0; i < 4; i++)
        #pragma unroll
        for (int j = 0; j < 4; j++)
            #pragma unroll
            for (int e = 0; e < 4; e++) acc[i][j][e] = 0.0f;

    float4 va[4], vb[4];

    // prefetch chunk 0
    {
        int ar = rowbase + lrow;
        #pragma unroll
        for (int j = 0; j < 4; j++) {
            va[j] = (ar < NN) ? *(const float4*)(x + (size_t)ar * INF_ + lko + j * 4)
                              : make_float4(0.f, 0.f, 0.f, 0.f);
            vb[j] = *(const float4*)(g_Wb + (size_t)(nbase + lrow) * INF_ + lko + j * 4);
        }
    }
    // store chunk 0 into stage 0
    #pragma unroll
    for (int j = 0; j < 4; j++) {
        int k0 = lko + j * 4;
        As[(k0 + 0) * SSTR + lrow] = tf32_of(va[j].x);
        As[(k0 + 1) * SSTR + lrow] = tf32_of(va[j].y);
        As[(k0 + 2) * SSTR + lrow] = tf32_of(va[j].z);
        As[(k0 + 3) * SSTR + lrow] = tf32_of(va[j].w);
        Bs[(k0 + 0) * SSTR + lrow] = tf32_of(vb[j].x);
        Bs[(k0 + 1) * SSTR + lrow] = tf32_of(vb[j].y);
        Bs[(k0 + 2) * SSTR + lrow] = tf32_of(vb[j].z);
        Bs[(k0 + 3) * SSTR + lrow] = tf32_of(vb[j].w);
    }
    __syncthreads();

    for (int c = 0; c < 8; c++) {
        const int st = c & 1;
        const uint32_t* Ac = As + st * STG_F;
        const uint32_t* Bc = Bs + st * STG_F;

        // prefetch next chunk to regs
        if (c < 7) {
            int kb = (c + 1) * KC;
            int ar = rowbase + lrow;
            #pragma unroll
            for (int j = 0; j < 4; j++) {
                va[j] = (ar < NN) ? *(const float4*)(x + (size_t)ar * INF_ + kb + lko + j * 4)
                                  : make_float4(0.f, 0.f, 0.f, 0.f);
                vb[j] = *(const float4*)(g_Wb + (size_t)(nbase + lrow) * INF_ + kb + lko + j * 4);
            }
        }

        // compute on current stage
        #pragma unroll
        for (int ks = 0; ks < 4; ks++) {
            uint32_t af[4][4], bf[4][2];
            const int k0 = ks * 8 + (lane & 3);
            const int mrow = wm * 64 + (lane >> 2);
            const int ncol = wn * 32 + (lane >> 2);
            #pragma unroll
            for (int mf = 0; mf < 4; mf++) {
                int m = mrow + mf * 16;
                af[mf][0] = Ac[k0 * SSTR + m];
                af[mf][1] = Ac[k0 * SSTR + m + 8];
                af[mf][2] = Ac[(k0 + 4) * SSTR + m];
                af[mf][3] = Ac[(k0 + 4) * SSTR + m + 8];
            }
            #pragma unroll
            for (int nf = 0; nf < 4; nf++) {
                int n = ncol + nf * 8;
                bf[nf][0] = Bc[k0 * SSTR + n];
                bf[nf][1] = Bc[(k0 + 4) * SSTR + n];
            }
            #pragma unroll
            for (int mf = 0; mf < 4; mf++)
                #pragma unroll
                for (int nf = 0; nf < 4; nf++)
                    mma_tf32(acc[mf][nf], af[mf], bf[nf]);
        }
        __syncthreads();

        // store prefetched chunk into the other stage
        if (c < 7) {
            uint32_t* An = As + ((c + 1) & 1) * STG_F;
            uint32_t* Bn = Bs + ((c + 1) & 1) * STG_F;
            #pragma unroll
            for (int j = 0; j < 4; j++) {
                int k0 = lko + j * 4;
                An[(k0 + 0) * SSTR + lrow] = tf32_of(va[j].x);
                An[(k0 + 1) * SSTR + lrow] = tf32_of(va[j].y);
                An[(k0 + 2) * SSTR + lrow] = tf32_of(va[j].z);
                An[(k0 + 3) * SSTR + lrow] = tf32_of(va[j].w);
                Bn[(k0 + 0) * SSTR + lrow] = tf32_of(vb[j].x);
                Bn[(k0 + 1) * SSTR + lrow] = tf32_of(vb[j].y);
                Bn[(k0 + 2) * SSTR + lrow] = tf32_of(vb[j].z);
                Bn[(k0 + 3) * SSTR + lrow] = tf32_of(vb[j].w);
            }
            __syncthreads();
        }
    }

    // epilogue: bias + store z
    #pragma unroll
    for (int mf = 0; mf < 4; mf++) {
        #pragma unroll
        for (int nf = 0; nf < 4; nf++) {
            int cc = wn * 32 + nf * 8 + (lane & 3) * 2;     // col within CTA
            int r0 = rowbase + wm * 64 + mf * 16 + (lane >> 2);
            float bx = s_bias[cc], by = s_bias[cc + 1];
            if (r0 < NN) {
                float2 v = make_float2(acc[mf][nf][0] + bx, acc[mf][nf][1] + by);
                *(float2*)(g_z + (size_t)r0 * HOUT + nbase + cc) = v;
            }
            if (r0 + 8 < NN) {
                float2 v = make_float2(acc[mf][nf][2] + bx, acc[mf][nf][3] + by);
                *(float2*)(g_z + (size_t)(r0 + 8) * HOUT + nbase + cc) = v;
            }
        }
    }
}

// ---------------- K1b: ai/aj dots from z ----------------
__global__ void __launch_bounds__(256) k_att()
{
    __shared__ float swi[HOUT], swj[HOUT];
    const int t = threadIdx.x;
    swi[t] = g_Wi2[t];
    swj[t] = g_Wj2[t];
    __syncthreads();
    const int wid = t >> 5, l = t & 31;
    const int n = blockIdx.x * 8 + wid;
    if (n >= NN) return;
    float4 z0 = *(const float4*)(g_z + (size_t)n * HOUT + l * 8);
    float4 z1 = *(const float4*)(g_z + (size_t)n * HOUT + l * 8 + 4);
    float si = z0.x * swi[l * 8 + 0] + z0.y * swi[l * 8 + 1] + z0.z * swi[l * 8 + 2]
             + z0.w * swi[l * 8 + 3] + z1.x * swi[l * 8 + 4] + z1.y * swi[l * 8 + 5]
             + z1.z * swi[l * 8 + 6] + z1.w * swi[l * 8 + 7];
    float sj = z0.x * swj[l * 8 + 0] + z0.y * swj[l * 8 + 1] + z0.z * swj[l * 8 + 2]
             + z0.w * swj[l * 8 + 3] + z1.x * swj[l * 8 + 4] + z1.y * swj[l * 8 + 5]
             + z1.z * swj[l * 8 + 6] + z1.w * swj[l * 8 + 7];
    #pragma unroll
    for (int o = 4; o >= 1; o >>= 1) {
        si += __shfl_xor_sync(0xffffffffu, si, o);
        sj += __shfl_xor_sync(0xffffffffu, sj, o);
    }
    if ((l & 7) == 0) {
        g_ai[n * HH + (l >> 3)] = si;
        g_aj[n * HH + (l >> 3)] = sj;
    }
}

// ---------------- K2: edge logits + leaky relu + exp; fused degree histogram ----------------
__global__ void __launch_bounds__(128) k_edge_logits(
    const float* __restrict__ edge_attr, const int* __restrict__ ei)
{
    __shared__ __align__(16) float sm_ea[128 * 68];
    __shared__ __align__(16) float sm_v[HH * EDF];
    __shared__ float sm_c[HH];
    const int t = threadIdx.x;
    const int ebase = blockIdx.x * 128;

    #pragma unroll
    for (int j = 0; j < 16; j++) {
        int f4 = t + 128 * j;
        int eeI = f4 >> 4, qf = (f4 & 15) * 4;
        float4 v = *(const float4*)(edge_attr + (size_t)(ebase + eeI) * EDF + qf);
        *(float4*)(sm_ea + eeI * 68 + qf) = v;
    }
    if (t < HH * EDF) sm_v[t] = g_v[t];
    if (t + 128 < HH * EDF) sm_v[t + 128] = g_v[t + 128];
    if (t < HH) sm_c[t] = g_catt[t];
    __syncthreads();

    int ge = ebase + t;
    int src = ei[ge];
    int dst = ei[EE + ge];
    float4 ai4 = *(const float4*)(g_ai + dst * HH);
    float4 aj4 = *(const float4*)(g_aj + src * HH);
    float ain[4] = {ai4.x, ai4.y, ai4.z, ai4.w};
    float ajn[4] = {aj4.x, aj4.y, aj4.z, aj4.w};

    float exv[4];
    #pragma unroll
    for (int h = 0; h < HH; h++) {
        float acc = sm_c[h];
        #pragma unroll
        for (int f4 = 0; f4 < 16; f4++) {
            float4 ev = *(const float4*)(sm_ea + t * 68 + f4 * 4);
            float4 vv = *(const float4*)(sm_v + h * EDF + f4 * 4);
            acc += ev.x * vv.x + ev.y * vv.y + ev.z * vv.z + ev.w * vv.w;
        }
        float a = acc + ain[h] + ajn[h];
        float e = (a > 0.0f) ? a : 0.2f * a;
        exv[h] = __expf(e);
    }
    *(float4*)(g_ex + (size_t)ge * 4) =
        make_float4(exv[0], exv[1], exv[2], exv[3]);
    atomicAdd(&g_deg[dst], 1);
}

// ---------------- CSR build: 3-stage scan + fill ----------------
__global__ void __launch_bounds__(256) k_scan_a()
{
    __shared__ int sh[256];
    int t = threadIdx.x;
    int idx = blockIdx.x * 256 + t;
    int v = (idx < NN) ? g_deg[idx] : 0;
    sh[t] = v;
    __syncthreads();
    #pragma unroll
    for (int d = 1; d < 256; d <<= 1) {
        int x = (t >= d) ? sh[t - d] : 0;
        __syncthreads();
        if (t >= d) sh[t] += x;
        __syncthreads();
    }
    if (idx < NN) g_off[idx] = sh[t] - v;
    if (t == 255) g_bsum[blockIdx.x] = sh[255];
}

__global__ void __launch_bounds__(256) k_scan_b(int nblocks)
{
    __shared__ int sh[256];
    int t = threadIdx.x;
    int v = (t < nblocks) ? g_bsum[t] : 0;
    sh[t] = v;
    __syncthreads();
    #pragma unroll
    for (int d = 1; d < 256; d <<= 1) {
        int x = (t >= d) ? sh[t - d] : 0;
        __syncthreads();
        if (t >= d) sh[t] += x;
        __syncthreads();
    }
    if (t < nblocks) g_bsum[t] = sh[t] - v;
}

__global__ void __launch_bounds__(256) k_scan_c()
{
    int idx = blockIdx.x * 256 + threadIdx.x;
    if (idx < NN) {
        int o = g_off[idx] + g_bsum[blockIdx.x];
        g_off[idx] = o;
        g_cur[idx] = o;
    }
    if (idx == 0) g_off[NN] = EE;
}

__global__ void __launch_bounds__(256) k_fill(const int* __restrict__ ei)
{
    int e = blockIdx.x * 256 + threadIdx.x;
    if (e >= EE) return;
    int src = ei[e];
    int dst = ei[EE + e];
    int pos = atomicAdd(&g_cur[dst], 1);
    g_csr_src[pos] = src;
    g_csr_eid[pos] = e;
}

// ---------------- K3: gather — softmax denom + out + s, no atomics ----------------
__global__ void __launch_bounds__(256) k_gather(
    const float* __restrict__ edge_attr, float* __restrict__ out)
{
    const int t = threadIdx.x;
    const int lane64 = t & 63;
    const int nl = t >> 6;
    const int n = blockIdx.x * 4 + nl;
    const int h = lane64 >> 4;
    const int q = lane64 & 15;

    const int beg = g_off[n];
    const int end = g_off[n + 1];

    float ss = 0.0f;
    for (int i = beg + q; i < end; i += 16)
        ss += g_ex[(size_t)g_csr_eid[i] * 4 + h];
    #pragma unroll
    for (int o = 8; o >= 1; o >>= 1)
        ss += __shfl_xor_sync(0xffffffffu, ss, o, 16);
    float inv = 1.0f / ss;

    float4 accO = make_float4(0.f, 0.f, 0.f, 0.f);
    float4 accS = make_float4(0.f, 0.f, 0.f, 0.f);
    for (int i = beg; i < end; i++) {
        int eid = g_csr_eid[i];
        int src = g_csr_src[i];
        float al = g_ex[(size_t)eid * 4 + h] * inv;
        if (q == 0) g_ex[(size_t)eid * 4 + h] = al;
        float4 z4 = *(const float4*)(g_z + (size_t)src * HOUT + lane64 * 4);
        accO.x = fmaf(al, z4.x, accO.x);
        accO.y = fmaf(al, z4.y, accO.y);
        accO.z = fmaf(al, z4.z, accO.z);
        accO.w = fmaf(al, z4.w, accO.w);
        float4 e4 = *(const float4*)(edge_attr + (size_t)eid * EDF + q * 4);
        accS.x = fmaf(al, e4.x, accS.x);
        accS.y = fmaf(al, e4.y, accS.y);
        accS.z = fmaf(al, e4.z, accS.z);
        accS.w = fmaf(al, e4.w, accS.w);
    }
    *(float4*)(out + (size_t)n * HOUT + lane64 * 4) = accO;
    *(float4*)(g_s + (((size_t)n * HH + h) * EDF) + q * 4) = accS;
}

// ---------------- K4: transpose normalized alpha [e][h] -> [h][E] ----------------
__global__ void __launch_bounds__(256) k_alpha_t(float* __restrict__ alphaOut)
{
    int e = blockIdx.x * 256 + threadIdx.x;
    if (e >= EE) return;
    float4 a4 = *(const float4*)(g_ex + (size_t)e * 4);
    alphaOut[0 * (size_t)EE + e] = a4.x;
    alphaOut[1 * (size_t)EE + e] = a4.y;
    alphaOut[2 * (size_t)EE + e] = a4.z;
    alphaOut[3 * (size_t)EE + e] = a4.w;
}

// ---------------- K5: out += s @ W_edge + (deg>0 ? b_edge : 0) ----------------
__global__ void __launch_bounds__(256) k_out_gemm(
    const float* __restrict__ W_edge, const float* __restrict__ b_edge,
    float* __restrict__ out)
{
    __shared__ __align__(16) float As[64 * 68];
    __shared__ __align__(16) float Bs[64 * 64];
    const int h = blockIdx.y;
    const int rowbase = blockIdx.x * 64;
    const int tid = threadIdx.x;
    const int tx = tid & 15, ty = tid >> 4;

    {
        const int lr = tid >> 2;
        const int lq = (tid & 3) * 4;
        #pragma unroll
        for (int j = 0; j < 4; j++) {
            int f = lq + j * 16;
            int row = rowbase + lr;
            float4 v = make_float4(0.f, 0.f, 0.f, 0.f);
            if (row < NN)
                v = *(const float4*)(g_s + (((size_t)row * HH + h) * EDF) + f);
            *(float4*)(As + lr * 68 + f) = v;
        }
        const int fr = tid >> 4;
        const int qn = (tid & 15) * 4;
        #pragma unroll
        for (int j = 0; j < 4; j++) {
            int fk = fr + j * 16;
            float4 w = *(const float4*)(W_edge + ((size_t)h * EDF + fk) * OUTF + qn);
            *(float4*)(Bs + fk * 64 + qn) = w;
        }
    }
    __syncthreads();

    float c[4][4];
    #pragma unroll
    for (int i = 0; i < 4; i++)
        #pragma unroll
        for (int j = 0; j < 4; j++) c[i][j] = 0.0f;

    #pragma unroll 16
    for (int kk = 0; kk < EDF; kk++) {
        float a0 = As[(ty * 4 + 0) * 68 + kk];
        float a1 = As[(ty * 4 + 1) * 68 + kk];
        float a2 = As[(ty * 4 + 2) * 68 + kk];
        float a3 = As[(ty * 4 + 3) * 68 + kk];
        float4 b = *(const float4*)(Bs + kk * 64 + tx * 4);
        c[0][0] += a0 * b.x; c[0][1] += a0 * b.y; c[0][2] += a0 * b.z; c[0][3] += a0 * b.w;
        c[1][0] += a1 * b.x; c[1][1] += a1 * b.y; c[1][2] += a1 * b.z; c[1][3] += a1 * b.w;
        c[2][0] += a2 * b.x; c[2][1] += a2 * b.y; c[2][2] += a2 * b.z; c[2][3] += a2 * b.w;
        c[3][0] += a3 * b.x; c[3][1] += a3 * b.y; c[3][2] += a3 * b.z; c[3][3] += a3 * b.w;
    }

    float4 be = *(const float4*)(b_edge + h * OUTF + tx * 4);

    #pragma unroll
    for (int i = 0; i < 4; i++) {
        int row = rowbase + ty * 4 + i;
        if (row < NN) {
            float flag = (g_off[row + 1] - g_off[row]) > 0 ? 1.0f : 0.0f;
            float* po = out + (size_t)row * HOUT + h * OUTF + tx * 4;
            float4 o4 = *(const float4*)po;
            o4.x += c[i][0] + flag * be.x;
            o4.y += c[i][1] + flag * be.y;
            o4.z += c[i][2] + flag * be.z;
            o4.w += c[i][3] + flag * be.w;
            *(float4*)po = o4;
        }
    }
}

// ---------------- launch ----------------
extern "C" void kernel_launch(void* const* d_in, const int* in_sizes, int n_in,
                              void* d_out, int out_size)
{
    const float* x      = (const float*)d_in[0];
    const int*   ei     = (const int*)d_in[1];
    const float* eattr  = (const float*)d_in[2];
    const float* W_fc   = (const float*)d_in[3];
    const float* b_fc   = (const float*)d_in[4];
    const float* W_att  = (const float*)d_in[5];
    const float* b_att  = (const float*)d_in[6];
    const float* W_edge = (const float*)d_in[7];
    const float* b_edge = (const float*)d_in[8];
    const float* W_eatt = (const float*)d_in[9];
    const float* b_eatt = (const float*)d_in[10];
    float* out = (float*)d_out;
    float* alphaOut = out + (size_t)NN * HOUT;

    const int SCAN_BLKS = (NN + 255) / 256;  // 196
    const int DYN_SMEM = 4 * STG_F * 4;      // 4 stages(2A+2B) * 4224 floats * 4B = 67584

    cudaFuncSetAttribute(k_node_tc, cudaFuncAttributeMaxDynamicSharedMemorySize,
                         DYN_SMEM);

    k_init<<<256, 256>>>(W_fc, W_att, b_att, W_eatt, b_eatt);
    k_node_tc<<<dim3((NN + 127) / 128, 2), 256, DYN_SMEM>>>(x, b_fc);
    k_att<<<(NN + 7) / 8, 256>>>();
    k_edge_logits<<<EE / 128, 128>>>(eattr, ei);
    k_scan_a<<<SCAN_BLKS, 256>>>();
    k_scan_b<<<1, 256>>>(SCAN_BLKS);
    k_scan_c<<<SCAN_BLKS, 256>>>();
    k_fill<<<(EE + 255) / 256, 256>>>(ei);
    k_gather<<<NN / 4, 256>>>(eattr, out);
    k_alpha_t<<<(EE + 255) / 256, 256>>>(alphaOut);
    k_out_gemm<<<dim3((NN + 63) / 64, HH), 256>>>(W_edge, b_edge, out);
}